// round 11
// baseline (speedup 1.0000x reference)
#include <cuda_runtime.h>
#include <cuda_bf16.h>
#include <math.h>
#include <stdint.h>

// Problem constants (B=4096, I=H=1024, 4H=4096)
#define MB 4096
#define KK 1024
#define NN 4096
#define HH 1024
#define MTOT 8192              // input rows stacked on h_prev rows
#define KTOT 3072              // 3 * KK  (split-bf16 segments)

// ---------------- scratch (allocation-free: device globals) ----------------
__device__ __align__(1024) __nv_bfloat16 g_Abig[(size_t)MTOT * KTOT];      // 48 MB
__device__ __align__(1024) __nv_bfloat16 g_Bbig[2][(size_t)NN * KTOT];     // 48 MB
__device__ float g_pre_i2h[(size_t)MB * NN];                               // 64 MB
__device__ float g_pre_h2h[(size_t)MB * NN];                               // 64 MB

// ========================= PTX helpers =========================
__device__ __forceinline__ uint32_t smem_u32(const void* p) {
    uint32_t a;
    asm("{ .reg .u64 t; cvta.to.shared.u64 t, %1; cvt.u32.u64 %0, t; }" : "=r"(a) : "l"(p));
    return a;
}
__device__ __forceinline__ void cp_async16(uint32_t saddr, const void* gaddr) {
    asm volatile("cp.async.cg.shared.global [%0], [%1], 16;" :: "r"(saddr), "l"(gaddr));
}
#define CP_COMMIT() asm volatile("cp.async.commit_group;" ::: "memory")
#define CP_WAIT_GROUP(n) asm volatile("cp.async.wait_group %0;" :: "n"(n) : "memory")

__device__ __forceinline__ void ldsm_x4(uint32_t& r0, uint32_t& r1, uint32_t& r2, uint32_t& r3, uint32_t addr) {
    asm volatile("ldmatrix.sync.aligned.m8n8.x4.shared.b16 {%0,%1,%2,%3}, [%4];"
        : "=r"(r0), "=r"(r1), "=r"(r2), "=r"(r3) : "r"(addr));
}
__device__ __forceinline__ void mma16816(float* d, uint32_t a0, uint32_t a1, uint32_t a2, uint32_t a3,
                                         uint32_t b0, uint32_t b1) {
    asm volatile("mma.sync.aligned.m16n8k16.row.col.f32.bf16.bf16.f32 "
        "{%0,%1,%2,%3}, {%4,%5,%6,%7}, {%8,%9}, {%0,%1,%2,%3};"
        : "+f"(d[0]), "+f"(d[1]), "+f"(d[2]), "+f"(d[3])
        : "r"(a0), "r"(a1), "r"(a2), "r"(a3), "r"(b0), "r"(b1));
}
__device__ __forceinline__ uint32_t sw128(uint32_t off) { return off ^ ((off >> 3) & 0x70); }

// ========================= conversion kernels =========================
// A' row r: [0,KK)=hi, [KK,2KK)=hi, [2KK,3KK)=lo  (rows 0..4095=input, 4096..8191=h_prev)
__global__ __launch_bounds__(256)
void convert_A(const float* __restrict__ input, const float* __restrict__ h_prev)
{
    size_t idx = (size_t)blockIdx.x * blockDim.x + threadIdx.x;   // pair index
    size_t e = idx * 2;
    size_t r = e / KK;
    int k = (int)(e % KK);
    const float* src = (r < MB) ? (input + r * KK) : (h_prev + (r - MB) * KK);
    float2 v = *reinterpret_cast<const float2*>(src + k);
    __nv_bfloat162 hi, lo;
    hi.x = __float2bfloat16_rn(v.x);
    hi.y = __float2bfloat16_rn(v.y);
    lo.x = __float2bfloat16_rn(v.x - __bfloat162float(hi.x));
    lo.y = __float2bfloat16_rn(v.y - __bfloat162float(hi.y));
    __nv_bfloat16* dst = g_Abig + r * KTOT;
    *reinterpret_cast<__nv_bfloat162*>(dst + k) = hi;
    *reinterpret_cast<__nv_bfloat162*>(dst + KK + k) = hi;
    *reinterpret_cast<__nv_bfloat162*>(dst + 2 * KK + k) = lo;
}

// Bt'[mat][n][*]: transpose of w[k][n]; segments [0,KK)=hi, [KK,2KK)=lo, [2KK,3KK)=hi
// Coalesced: 64x64 tile staged in smem, bf16x2 stores contiguous along k.
__global__ __launch_bounds__(256)
void convert_B(const float* __restrict__ w0, const float* __restrict__ w1)
{
    __shared__ float tile[64][65];
    const int mat = blockIdx.z;
    const float* w = mat ? w1 : w0;
    const int k0 = blockIdx.y * 64;
    const int n0 = blockIdx.x * 64;
    const int tid = threadIdx.x;

    // load 64 k-rows x 64 n-cols, float4-coalesced
    {
        const int c = (tid & 15) * 4;
        for (int r = tid >> 4; r < 64; r += 16) {
            float4 v = *reinterpret_cast<const float4*>(w + (size_t)(k0 + r) * NN + n0 + c);
            tile[r][c] = v.x; tile[r][c + 1] = v.y; tile[r][c + 2] = v.z; tile[r][c + 3] = v.w;
        }
    }
    __syncthreads();

    __nv_bfloat16* dst = g_Bbig[mat];
    for (int it = tid; it < 64 * 32; it += 256) {
        const int n = it >> 5;
        const int k = (it & 31) * 2;
        float x0 = tile[k][n];
        float x1 = tile[k + 1][n];
        __nv_bfloat162 hi, lo;
        hi.x = __float2bfloat16_rn(x0);
        hi.y = __float2bfloat16_rn(x1);
        lo.x = __float2bfloat16_rn(x0 - __bfloat162float(hi.x));
        lo.y = __float2bfloat16_rn(x1 - __bfloat162float(hi.y));
        __nv_bfloat16* row = dst + (size_t)(n0 + n) * KTOT + k0;
        *reinterpret_cast<__nv_bfloat162*>(row + k) = hi;
        *reinterpret_cast<__nv_bfloat162*>(row + KK + k) = lo;
        *reinterpret_cast<__nv_bfloat162*>(row + 2 * KK + k) = hi;
    }
}

// ========================= mma.sync GEMM =========================
// C[128,256] tiles; A[MTOT,KTOT] row-major bf16, Bt[n][k] bf16 (K-major).
#define BM 128
#define BN 256
#define BK 64
#define GSTAGES 4
#define NSTEPS (KTOT / BK)             // 48
#define GTHREADS 256

#define A_STAGE_BYTES (BM * 128)       // 16384 (128B swizzled rows)
#define B_STAGE_BYTES (BN * 128)       // 32768
#define STAGE_BYTES (A_STAGE_BYTES + B_STAGE_BYTES)   // 49152
#define GSMEM_TOTAL (GSTAGES * STAGE_BYTES)           // 196608

__device__ __forceinline__ void load_stage(uint32_t sbase, int s, int kc, int tid,
                                           const __nv_bfloat16* gA, const __nv_bfloat16* gB)
{
    const int kbase = kc * BK;
    const uint32_t stage = sbase + s * STAGE_BYTES;
    #pragma unroll
    for (int j = 0; j < 12; j++) {
        int idx = tid + j * GTHREADS;   // 0..3071
        if (idx < 1024) {               // A: 128 rows x 8 x 16B
            int row = idx >> 3, ch = idx & 7;
            uint32_t off = (uint32_t)(row * 128 + ch * 16);
            cp_async16(stage + sw128(off), gA + (size_t)row * KTOT + kbase + ch * 8);
        } else {                        // B: 256 rows x 8 x 16B
            int b = idx - 1024;
            int row = b >> 3, ch = b & 7;
            uint32_t off = (uint32_t)(row * 128 + ch * 16);
            cp_async16(stage + A_STAGE_BYTES + sw128(off), gB + (size_t)row * KTOT + kbase + ch * 8);
        }
    }
}

__global__ __launch_bounds__(GTHREADS, 1)
void gemm_bf16x3()
{
    extern __shared__ char gsm[];
    const uint32_t sbase = smem_u32(gsm);
    const int tid = threadIdx.x;
    const int wid = tid >> 5;
    const int lid = tid & 31;
    const int warp_m = wid >> 2;        // 0..1 -> 64-row slab
    const int warp_n = wid & 3;         // 0..3 -> 64-col slab

    const int tileN = blockIdx.x;       // 0..15
    const int tileM = blockIdx.y;       // 0..63
    const int mat = (tileM >= 32) ? 1 : 0;
    const __nv_bfloat16* gA = g_Abig + (size_t)tileM * BM * KTOT;
    const __nv_bfloat16* gB = g_Bbig[mat] + (size_t)tileN * BN * KTOT;

    float acc[4][8][4];
    #pragma unroll
    for (int mi = 0; mi < 4; mi++)
        #pragma unroll
        for (int ni = 0; ni < 8; ni++)
            #pragma unroll
            for (int r = 0; r < 4; r++)
                acc[mi][ni][r] = 0.0f;

    // prologue: fill first 3 stages (one commit group each)
    load_stage(sbase, 0, 0, tid, gA, gB);
    CP_COMMIT();
    load_stage(sbase, 1, 1, tid, gA, gB);
    CP_COMMIT();
    load_stage(sbase, 2, 2, tid, gA, gB);
    CP_COMMIT();

    // per-lane ldmatrix offsets (within a stage, unswizzled)
    const int a_row_l = warp_m * 64 + (lid & 15);
    const int a_kb_l = (lid >> 4) * 16;
    const int b_row_l = warp_n * 64 + ((lid >> 4) & 1) * 8 + (lid & 7);
    const int b_kb_l = ((lid >> 3) & 1) * 16;

    // double-buffered k-slice operand registers
    uint32_t abuf[2][4][4];
    uint32_t bbuf[2][8][2];

    for (int i = 0; i < NSTEPS; i++) {
        const int s = i & 3;
        // Exactly one group committed per iteration (empty in the tail),
        // so waiting for <=2 outstanding guarantees stage i's group is done.
        CP_WAIT_GROUP(2);
        __syncthreads();                // all warps finished reading the slot being refilled

        if (i + 3 < NSTEPS)
            load_stage(sbase, (i + 3) & 3, i + 3, tid, gA, gB);
        CP_COMMIT();                    // uniform group accounting (may be empty)

        const uint32_t aS = sbase + s * STAGE_BYTES;
        const uint32_t bS = aS + A_STAGE_BYTES;

        // prefetch k-slice 0 into buffer 0
        #pragma unroll
        for (int mi = 0; mi < 4; mi++) {
            uint32_t off = (uint32_t)((a_row_l + mi * 16) * 128 + a_kb_l);
            ldsm_x4(abuf[0][mi][0], abuf[0][mi][1], abuf[0][mi][2], abuf[0][mi][3], aS + sw128(off));
        }
        #pragma unroll
        for (int np = 0; np < 4; np++) {
            uint32_t off = (uint32_t)((b_row_l + np * 16) * 128 + b_kb_l);
            uint32_t r0, r1, r2, r3;
            ldsm_x4(r0, r1, r2, r3, bS + sw128(off));
            bbuf[0][np * 2][0] = r0; bbuf[0][np * 2][1] = r1;
            bbuf[0][np * 2 + 1][0] = r2; bbuf[0][np * 2 + 1][1] = r3;
        }

        #pragma unroll
        for (int ks = 0; ks < 4; ks++) {
            const int cur = ks & 1;
            const int nxt = cur ^ 1;
            if (ks < 3) {   // prefetch next k-slice while current MMAs run
                #pragma unroll
                for (int mi = 0; mi < 4; mi++) {
                    uint32_t off = (uint32_t)((a_row_l + mi * 16) * 128 + (ks + 1) * 32 + a_kb_l);
                    ldsm_x4(abuf[nxt][mi][0], abuf[nxt][mi][1], abuf[nxt][mi][2], abuf[nxt][mi][3], aS + sw128(off));
                }
                #pragma unroll
                for (int np = 0; np < 4; np++) {
                    uint32_t off = (uint32_t)((b_row_l + np * 16) * 128 + (ks + 1) * 32 + b_kb_l);
                    uint32_t r0, r1, r2, r3;
                    ldsm_x4(r0, r1, r2, r3, bS + sw128(off));
                    bbuf[nxt][np * 2][0] = r0; bbuf[nxt][np * 2][1] = r1;
                    bbuf[nxt][np * 2 + 1][0] = r2; bbuf[nxt][np * 2 + 1][1] = r3;
                }
            }
            #pragma unroll
            for (int mi = 0; mi < 4; mi++)
                #pragma unroll
                for (int ni = 0; ni < 8; ni++)
                    mma16816(acc[mi][ni], abuf[cur][mi][0], abuf[cur][mi][1],
                             abuf[cur][mi][2], abuf[cur][mi][3],
                             bbuf[cur][ni][0], bbuf[cur][ni][1]);
        }
    }

    // store C
    float* gC = ((tileM < 32) ? (g_pre_i2h + (size_t)tileM * BM * NN)
                              : (g_pre_h2h + (size_t)(tileM - 32) * BM * NN))
                + (size_t)tileN * BN;
    const int mrow = warp_m * 64 + (lid >> 2);
    const int ncol = warp_n * 64 + (lid & 3) * 2;
    #pragma unroll
    for (int mi = 0; mi < 4; mi++) {
        #pragma unroll
        for (int ni = 0; ni < 8; ni++) {
            float* p0 = gC + (size_t)(mrow + mi * 16) * NN + ncol + ni * 8;
            float* p1 = gC + (size_t)(mrow + mi * 16 + 8) * NN + ncol + ni * 8;
            *reinterpret_cast<float2*>(p0) = make_float2(acc[mi][ni][0], acc[mi][ni][1]);
            *reinterpret_cast<float2*>(p1) = make_float2(acc[mi][ni][2], acc[mi][ni][3]);
        }
    }
}

// ========================= LN + gates epilogue =========================
#define EPS 1e-6f

__device__ __forceinline__ float sigm(float x) { return 1.0f / (1.0f + __expf(-x)); }
__device__ __forceinline__ float fast_tanh(float x) {
    float ax = fminf(fabsf(x), 15.0f);
    float t = __expf(2.0f * ax);
    float r = (t - 1.0f) / (t + 1.0f);
    return copysignf(r, x);
}

__device__ void block_reduce2(float& s, float& q)
{
    __shared__ __align__(16) float rs[8], rq[8];
    __shared__ float bs, bq;
    #pragma unroll
    for (int o = 16; o > 0; o >>= 1) {
        s += __shfl_down_sync(0xffffffffu, s, o);
        q += __shfl_down_sync(0xffffffffu, q, o);
    }
    const int w = threadIdx.x >> 5, l = threadIdx.x & 31;
    __syncthreads();
    if (l == 0) { rs[w] = s; rq[w] = q; }
    __syncthreads();
    if (threadIdx.x == 0) {
        float a = 0.0f, b = 0.0f;
        #pragma unroll
        for (int i = 0; i < 8; i++) { a += rs[i]; b += rq[i]; }
        bs = a; bq = b;
    }
    __syncthreads();
    s = bs; q = bq;
}

__global__ __launch_bounds__(256)
void lstm_epilogue(const float* __restrict__ c_prev,
                   const float* __restrict__ b_i2h, const float* __restrict__ b_h2h,
                   const float* __restrict__ g_i2h, const float* __restrict__ be_i2h,
                   const float* __restrict__ g_h2h, const float* __restrict__ be_h2h,
                   const float* __restrict__ g_c,   const float* __restrict__ be_c,
                   float* __restrict__ out)
{
    __shared__ __align__(16) float sh_g[NN];
    __shared__ __align__(16) float sh_h[NN];

    const int r = blockIdx.x;
    const int tid = threadIdx.x;
    const float* hi = g_pre_i2h + (size_t)r * NN;
    const float* hh = g_pre_h2h + (size_t)r * NN;

    // --- LN stats for i2h row (float4) ---
    float s = 0.0f, q = 0.0f;
    for (int j = tid * 4; j < NN; j += 1024) {
        float4 v = *reinterpret_cast<const float4*>(hi + j);
        float4 b = *reinterpret_cast<const float4*>(b_i2h + j);
        v.x += b.x; v.y += b.y; v.z += b.z; v.w += b.w;
        *reinterpret_cast<float4*>(sh_g + j) = v;
        s += v.x + v.y + v.z + v.w;
        q += v.x * v.x + v.y * v.y + v.z * v.z + v.w * v.w;
    }
    block_reduce2(s, q);
    const float m1 = s / (float)NN;
    const float v1 = (q - s * s / (float)NN) / (float)(NN - 1);
    const float inv1 = 1.0f / (sqrtf(v1) + EPS);

    // --- LN stats for h2h row ---
    s = 0.0f; q = 0.0f;
    for (int j = tid * 4; j < NN; j += 1024) {
        float4 v = *reinterpret_cast<const float4*>(hh + j);
        float4 b = *reinterpret_cast<const float4*>(b_h2h + j);
        v.x += b.x; v.y += b.y; v.z += b.z; v.w += b.w;
        *reinterpret_cast<float4*>(sh_h + j) = v;
        s += v.x + v.y + v.z + v.w;
        q += v.x * v.x + v.y * v.y + v.z * v.z + v.w * v.w;
    }
    block_reduce2(s, q);
    const float m2 = s / (float)NN;
    const float v2 = (q - s * s / (float)NN) / (float)(NN - 1);
    const float inv2 = 1.0f / (sqrtf(v2) + EPS);

    // --- normalized sum -> gates ---
    for (int j = tid * 4; j < NN; j += 1024) {
        float4 x = *reinterpret_cast<const float4*>(sh_g + j);
        float4 y = *reinterpret_cast<const float4*>(sh_h + j);
        float4 ga = *reinterpret_cast<const float4*>(g_i2h + j);
        float4 ba = *reinterpret_cast<const float4*>(be_i2h + j);
        float4 gb = *reinterpret_cast<const float4*>(g_h2h + j);
        float4 bb = *reinterpret_cast<const float4*>(be_h2h + j);
        float4 o;
        o.x = ga.x * ((x.x - m1) * inv1) + ba.x + gb.x * ((y.x - m2) * inv2) + bb.x;
        o.y = ga.y * ((x.y - m1) * inv1) + ba.y + gb.y * ((y.y - m2) * inv2) + bb.y;
        o.z = ga.z * ((x.z - m1) * inv1) + ba.z + gb.z * ((y.z - m2) * inv2) + bb.z;
        o.w = ga.w * ((x.w - m1) * inv1) + ba.w + gb.w * ((y.w - m2) * inv2) + bb.w;
        *reinterpret_cast<float4*>(sh_g + j) = o;
    }
    __syncthreads();

    // --- cell pre-activation ---
    s = 0.0f; q = 0.0f;
    for (int k = tid * 4; k < HH; k += 1024) {
        float4 ig = *reinterpret_cast<const float4*>(sh_g + k);
        float4 fg = *reinterpret_cast<const float4*>(sh_g + HH + k);
        float4 ug = *reinterpret_cast<const float4*>(sh_g + 2 * HH + k);
        float4 og = *reinterpret_cast<const float4*>(sh_g + 3 * HH + k);
        float4 cv = *reinterpret_cast<const float4*>(c_prev + (size_t)r * HH + k);
        float4 cp;
        cp.x = cv.x * sigm(fg.x + 1.0f) + fast_tanh(ug.x) * sigm(ig.x);
        cp.y = cv.y * sigm(fg.y + 1.0f) + fast_tanh(ug.y) * sigm(ig.y);
        cp.z = cv.z * sigm(fg.z + 1.0f) + fast_tanh(ug.z) * sigm(ig.z);
        cp.w = cv.w * sigm(fg.w + 1.0f) + fast_tanh(ug.w) * sigm(ig.w);
        *reinterpret_cast<float4*>(sh_h + k) = cp;
        *reinterpret_cast<float4*>(sh_h + HH + k) = og;
        s += cp.x + cp.y + cp.z + cp.w;
        q += cp.x * cp.x + cp.y * cp.y + cp.z * cp.z + cp.w * cp.w;
    }
    block_reduce2(s, q);
    const float m3 = s / (float)HH;
    const float v3 = (q - s * s / (float)HH) / (float)(HH - 1);
    const float inv3 = 1.0f / (sqrtf(v3) + EPS);

    // --- c = LN(cpre), h = sigmoid(o) * tanh(c) ---
    float* out_h = out;
    float* out_c = out + (size_t)MB * HH;
    for (int k = tid * 4; k < HH; k += 1024) {
        float4 cp = *reinterpret_cast<const float4*>(sh_h + k);
        float4 og = *reinterpret_cast<const float4*>(sh_h + HH + k);
        float4 gc = *reinterpret_cast<const float4*>(g_c + k);
        float4 bc = *reinterpret_cast<const float4*>(be_c + k);
        float4 c, h;
        c.x = gc.x * ((cp.x - m3) * inv3) + bc.x;
        c.y = gc.y * ((cp.y - m3) * inv3) + bc.y;
        c.z = gc.z * ((cp.z - m3) * inv3) + bc.z;
        c.w = gc.w * ((cp.w - m3) * inv3) + bc.w;
        h.x = sigm(og.x) * fast_tanh(c.x);
        h.y = sigm(og.y) * fast_tanh(c.y);
        h.z = sigm(og.z) * fast_tanh(c.z);
        h.w = sigm(og.w) * fast_tanh(c.w);
        *reinterpret_cast<float4*>(out_h + (size_t)r * HH + k) = h;
        *reinterpret_cast<float4*>(out_c + (size_t)r * HH + k) = c;
    }
}

// ========================= launch =========================
extern "C" void kernel_launch(void* const* d_in, const int* in_sizes, int n_in,
                              void* d_out, int out_size)
{
    const float* input  = (const float*)d_in[0];
    const float* h_prev = (const float*)d_in[1];
    const float* c_prev = (const float*)d_in[2];
    const float* w_i2h  = (const float*)d_in[3];
    const float* b_i2h  = (const float*)d_in[4];
    const float* w_h2h  = (const float*)d_in[5];
    const float* b_h2h  = (const float*)d_in[6];
    const float* g_i2h  = (const float*)d_in[7];
    const float* be_i2h = (const float*)d_in[8];
    const float* g_h2h  = (const float*)d_in[9];
    const float* be_h2h = (const float*)d_in[10];
    const float* g_c    = (const float*)d_in[11];
    const float* be_c   = (const float*)d_in[12];
    float* out = (float*)d_out;

    cudaFuncSetAttribute(gemm_bf16x3, cudaFuncAttributeMaxDynamicSharedMemorySize, GSMEM_TOTAL);

    // split-bf16 operand prep
    convert_A<<<(MTOT * KK / 2) / 256, 256>>>(input, h_prev);
    convert_B<<<dim3(NN / 64, KK / 64, 2), 256>>>(w_i2h, w_h2h);

    // fused dual GEMM on HMMA (K'=3072 covers hi*hi + hi*lo + lo*hi)
    gemm_bf16x3<<<dim3(NN / BN, MTOT / BM), GTHREADS, GSMEM_TOTAL>>>();

    lstm_epilogue<<<MB, 256>>>(c_prev, b_i2h, b_h2h, g_i2h, be_i2h,
                               g_h2h, be_h2h, g_c, be_c, out);
}

// round 12
// speedup vs baseline: 1.3586x; 1.3586x over previous
#include <cuda_runtime.h>
#include <math.h>
#include <stdint.h>

// Problem constants (B=4096, I=H=1024, 4H=4096)
#define MB 4096
#define KK 1024
#define NN 4096
#define HH 1024
#define MTOT 8192              // input rows stacked on h_prev rows

// ---------------- scratch (allocation-free: device globals) ----------------
// A' fragment-major: [mb(64)][ks(32)][mt(8)][kc(4)][lane(32)][j(4)] floats = 32 MB
__device__ __align__(1024) float g_Atf[(size_t)MTOT * KK];
// B' fragment-major: [mat][nb(16)][ks(32)][nt(32)][kc(4)][lane(32)][jb(2)] floats = 32 MB
__device__ __align__(1024) float g_Btf[2][(size_t)NN * KK];
__device__ float g_pre_i2h[(size_t)MB * NN];                               // 64 MB
__device__ float g_pre_h2h[(size_t)MB * NN];                               // 64 MB

// ========================= PTX helpers =========================
__device__ __forceinline__ uint32_t smem_u32(const void* p) {
    uint32_t a;
    asm("{ .reg .u64 t; cvta.to.shared.u64 t, %1; cvt.u32.u64 %0, t; }" : "=r"(a) : "l"(p));
    return a;
}
__device__ __forceinline__ void cp_async16(uint32_t saddr, const void* gaddr) {
    asm volatile("cp.async.cg.shared.global [%0], [%1], 16;" :: "r"(saddr), "l"(gaddr));
}
#define CP_COMMIT() asm volatile("cp.async.commit_group;" ::: "memory")
#define CP_WAIT_GROUP(n) asm volatile("cp.async.wait_group %0;" :: "n"(n) : "memory")

__device__ __forceinline__ uint32_t f2tf32(float x) {
    uint32_t r;
    asm("cvt.rna.tf32.f32 %0, %1;" : "=r"(r) : "f"(x));
    return r;
}
__device__ __forceinline__ void mma_tf32(float* d, uint32_t a0, uint32_t a1, uint32_t a2, uint32_t a3,
                                         uint32_t b0, uint32_t b1) {
    asm volatile("mma.sync.aligned.m16n8k8.row.col.f32.tf32.tf32.f32 "
        "{%0,%1,%2,%3}, {%4,%5,%6,%7}, {%8,%9}, {%0,%1,%2,%3};"
        : "+f"(d[0]), "+f"(d[1]), "+f"(d[2]), "+f"(d[3])
        : "r"(a0), "r"(a1), "r"(a2), "r"(a3), "r"(b0), "r"(b1));
}

// ========================= conversion kernels =========================
// A': one thread per (mb,ks,mt,kc,lane); writes its 4 fragment regs as float4.
// a0=A[m][k], a1=A[m+8][k], a2=A[m][k+4], a3=A[m+8][k+4]; m=mb*128+mt*16+(l>>2), k=ks*32+kc*8+(l&3)
__global__ __launch_bounds__(256)
void convert_A(const float* __restrict__ input, const float* __restrict__ h_prev)
{
    const uint32_t t = blockIdx.x * 256 + threadIdx.x;   // 0 .. 2^21-1
    const int l  = t & 31;
    const int kc = (t >> 5) & 3;
    const int mt = (t >> 7) & 7;
    const int ks = (t >> 10) & 31;
    const int mb = t >> 15;
    const int m = mb * 128 + mt * 16 + (l >> 2);
    const int k = ks * 32 + kc * 8 + (l & 3);
    const float* src = (m < MB) ? (input + (size_t)m * KK) : (h_prev + (size_t)(m - MB) * KK);
    const float* src8 = (m + 8 < MB) ? (input + (size_t)(m + 8) * KK) : (h_prev + (size_t)(m + 8 - MB) * KK);
    uint4 o;
    o.x = f2tf32(src[k]);
    o.y = f2tf32(src8[k]);
    o.z = f2tf32(src[k + 4]);
    o.w = f2tf32(src8[k + 4]);
    *reinterpret_cast<uint4*>(g_Atf + (size_t)t * 4) = o;
}

// B': one thread per (nb,ks,nt,kc,lane); writes b0,b1 as float2.
// b0=w[k][n], b1=w[k+4][n]; n=nb*256+nt*8+(l>>2), k=ks*32+kc*8+(l&3)
__global__ __launch_bounds__(256)
void convert_B(const float* __restrict__ w0, const float* __restrict__ w1)
{
    const uint32_t t = blockIdx.x * 256 + threadIdx.x;   // 0 .. 2^21-1
    const int mat = blockIdx.z;
    const float* w = mat ? w1 : w0;
    const int l  = t & 31;
    const int kc = (t >> 5) & 3;
    const int nt = (t >> 7) & 31;
    const int ks = (t >> 12) & 31;
    const int nb = t >> 17;
    const int n = nb * 256 + nt * 8 + (l >> 2);
    const int k = ks * 32 + kc * 8 + (l & 3);
    uint2 o;
    o.x = f2tf32(w[(size_t)k * NN + n]);
    o.y = f2tf32(w[(size_t)(k + 4) * NN + n]);
    *reinterpret_cast<uint2*>(g_Btf[mat] + (size_t)t * 2) = o;
}

// ========================= tf32 mma.sync GEMM =========================
// C[128,256] tiles; operands pre-permuted in fragment-major order.
#define BM 128
#define BN 256
#define BK 32
#define GSTAGES 4
#define NSTEPS (KK / BK)               // 32
#define GTHREADS 256

#define A_STAGE_BYTES (8 * 4 * 32 * 16)    // 16384: [mt][kc][lane][4 floats]
#define B_STAGE_BYTES (32 * 4 * 32 * 8)    // 32768: [nt][kc][lane][2 floats]
#define STAGE_BYTES (A_STAGE_BYTES + B_STAGE_BYTES)   // 49152
#define GSMEM_TOTAL (GSTAGES * STAGE_BYTES)           // 196608

__device__ __forceinline__ void load_stage(uint32_t sbase, int s, int kstage, int tid,
                                           const float* gA, const float* gB)
{
    const uint32_t stage = sbase + s * STAGE_BYTES;
    const float* Asrc = gA + (size_t)kstage * (A_STAGE_BYTES / 4);
    const float* Bsrc = gB + (size_t)kstage * (B_STAGE_BYTES / 4);
    #pragma unroll
    for (int j = 0; j < 12; j++) {
        int idx = tid + j * GTHREADS;   // 0..3071 (16B units)
        if (idx < 1024) {
            cp_async16(stage + idx * 16, Asrc + idx * 4);
        } else {
            int b = idx - 1024;
            cp_async16(stage + A_STAGE_BYTES + b * 16, Bsrc + b * 4);
        }
    }
}

__global__ __launch_bounds__(GTHREADS, 1)
void gemm_tf32()
{
    extern __shared__ char gsm[];
    const uint32_t sbase = smem_u32(gsm);
    const int tid = threadIdx.x;
    const int wid = tid >> 5;
    const int lid = tid & 31;
    const int warp_m = wid >> 2;        // 0..1 -> 64-row slab (4 mtiles)
    const int warp_n = wid & 3;         // 0..3 -> 64-col slab (8 ntiles)

    const int tileN = blockIdx.x;       // 0..15
    const int tileM = blockIdx.y;       // 0..63
    const int mat = (tileM >= 32) ? 1 : 0;
    // A' per (mb): 32 kstages x 16KB; B' per (nb): 32 kstages x 32KB
    const float* gA = g_Atf + (size_t)tileM * 32 * (A_STAGE_BYTES / 4);
    const float* gB = g_Btf[mat] + (size_t)tileN * 32 * (B_STAGE_BYTES / 4);

    float acc[4][8][4];
    #pragma unroll
    for (int mi = 0; mi < 4; mi++)
        #pragma unroll
        for (int ni = 0; ni < 8; ni++)
            #pragma unroll
            for (int r = 0; r < 4; r++)
                acc[mi][ni][r] = 0.0f;

    // prologue: fill first 3 stages (one commit group each)
    load_stage(sbase, 0, 0, tid, gA, gB);
    CP_COMMIT();
    load_stage(sbase, 1, 1, tid, gA, gB);
    CP_COMMIT();
    load_stage(sbase, 2, 2, tid, gA, gB);
    CP_COMMIT();

    for (int i = 0; i < NSTEPS; i++) {
        const int s = i & 3;
        // one group committed per iteration (empty in tail) -> <=2 outstanding
        // guarantees stage i's group has landed.
        CP_WAIT_GROUP(2);
        __syncthreads();

        if (i + 3 < NSTEPS)
            load_stage(sbase, (i + 3) & 3, i + 3, tid, gA, gB);
        CP_COMMIT();

        const uint32_t aS = sbase + s * STAGE_BYTES;
        const uint32_t bS = aS + A_STAGE_BYTES;

        #pragma unroll
        for (int kc = 0; kc < 4; kc++) {
            uint32_t a[4][4];
            #pragma unroll
            for (int mi = 0; mi < 4; mi++) {
                const int mt = warp_m * 4 + mi;
                uint32_t off = aS + (uint32_t)(((mt * 4 + kc) * 32 + lid) * 16);
                asm volatile("ld.shared.v4.b32 {%0,%1,%2,%3}, [%4];"
                    : "=r"(a[mi][0]), "=r"(a[mi][1]), "=r"(a[mi][2]), "=r"(a[mi][3]) : "r"(off));
            }
            uint32_t b[8][2];
            #pragma unroll
            for (int ni = 0; ni < 8; ni++) {
                const int nt = warp_n * 8 + ni;
                uint32_t off = bS + (uint32_t)(((nt * 4 + kc) * 32 + lid) * 8);
                asm volatile("ld.shared.v2.b32 {%0,%1}, [%2];"
                    : "=r"(b[ni][0]), "=r"(b[ni][1]) : "r"(off));
            }
            #pragma unroll
            for (int mi = 0; mi < 4; mi++)
                #pragma unroll
                for (int ni = 0; ni < 8; ni++)
                    mma_tf32(acc[mi][ni], a[mi][0], a[mi][1], a[mi][2], a[mi][3],
                             b[ni][0], b[ni][1]);
        }
    }

    // store C (D layout: d0,d1 -> row lid>>2, cols (lid&3)*2,+1; d2,d3 -> row+8)
    float* gC = ((tileM < 32) ? (g_pre_i2h + (size_t)tileM * BM * NN)
                              : (g_pre_h2h + (size_t)(tileM - 32) * BM * NN))
                + (size_t)tileN * BN;
    const int mrow = warp_m * 64 + (lid >> 2);
    const int ncol = warp_n * 64 + (lid & 3) * 2;
    #pragma unroll
    for (int mi = 0; mi < 4; mi++) {
        #pragma unroll
        for (int ni = 0; ni < 8; ni++) {
            float* p0 = gC + (size_t)(mrow + mi * 16) * NN + ncol + ni * 8;
            float* p1 = gC + (size_t)(mrow + mi * 16 + 8) * NN + ncol + ni * 8;
            *reinterpret_cast<float2*>(p0) = make_float2(acc[mi][ni][0], acc[mi][ni][1]);
            *reinterpret_cast<float2*>(p1) = make_float2(acc[mi][ni][2], acc[mi][ni][3]);
        }
    }
}

// ========================= LN + gates epilogue =========================
#define EPS 1e-6f

__device__ __forceinline__ float sigm(float x) { return 1.0f / (1.0f + __expf(-x)); }
__device__ __forceinline__ float fast_tanh(float x) {
    float ax = fminf(fabsf(x), 15.0f);
    float t = __expf(2.0f * ax);
    float r = (t - 1.0f) / (t + 1.0f);
    return copysignf(r, x);
}

__device__ void block_reduce2(float& s, float& q)
{
    __shared__ __align__(16) float rs[8], rq[8];
    __shared__ float bs, bq;
    #pragma unroll
    for (int o = 16; o > 0; o >>= 1) {
        s += __shfl_down_sync(0xffffffffu, s, o);
        q += __shfl_down_sync(0xffffffffu, q, o);
    }
    const int w = threadIdx.x >> 5, l = threadIdx.x & 31;
    __syncthreads();
    if (l == 0) { rs[w] = s; rq[w] = q; }
    __syncthreads();
    if (threadIdx.x == 0) {
        float a = 0.0f, b = 0.0f;
        #pragma unroll
        for (int i = 0; i < 8; i++) { a += rs[i]; b += rq[i]; }
        bs = a; bq = b;
    }
    __syncthreads();
    s = bs; q = bq;
}

__global__ __launch_bounds__(256)
void lstm_epilogue(const float* __restrict__ c_prev,
                   const float* __restrict__ b_i2h, const float* __restrict__ b_h2h,
                   const float* __restrict__ g_i2h, const float* __restrict__ be_i2h,
                   const float* __restrict__ g_h2h, const float* __restrict__ be_h2h,
                   const float* __restrict__ g_c,   const float* __restrict__ be_c,
                   float* __restrict__ out)
{
    __shared__ __align__(16) float sh_g[NN];
    __shared__ __align__(16) float sh_h[NN];

    const int r = blockIdx.x;
    const int tid = threadIdx.x;
    const float* hi = g_pre_i2h + (size_t)r * NN;
    const float* hh = g_pre_h2h + (size_t)r * NN;

    float s = 0.0f, q = 0.0f;
    for (int j = tid * 4; j < NN; j += 1024) {
        float4 v = *reinterpret_cast<const float4*>(hi + j);
        float4 b = *reinterpret_cast<const float4*>(b_i2h + j);
        v.x += b.x; v.y += b.y; v.z += b.z; v.w += b.w;
        *reinterpret_cast<float4*>(sh_g + j) = v;
        s += v.x + v.y + v.z + v.w;
        q += v.x * v.x + v.y * v.y + v.z * v.z + v.w * v.w;
    }
    block_reduce2(s, q);
    const float m1 = s / (float)NN;
    const float v1 = (q - s * s / (float)NN) / (float)(NN - 1);
    const float inv1 = 1.0f / (sqrtf(v1) + EPS);

    s = 0.0f; q = 0.0f;
    for (int j = tid * 4; j < NN; j += 1024) {
        float4 v = *reinterpret_cast<const float4*>(hh + j);
        float4 b = *reinterpret_cast<const float4*>(b_h2h + j);
        v.x += b.x; v.y += b.y; v.z += b.z; v.w += b.w;
        *reinterpret_cast<float4*>(sh_h + j) = v;
        s += v.x + v.y + v.z + v.w;
        q += v.x * v.x + v.y * v.y + v.z * v.z + v.w * v.w;
    }
    block_reduce2(s, q);
    const float m2 = s / (float)NN;
    const float v2 = (q - s * s / (float)NN) / (float)(NN - 1);
    const float inv2 = 1.0f / (sqrtf(v2) + EPS);

    for (int j = tid * 4; j < NN; j += 1024) {
        float4 x = *reinterpret_cast<const float4*>(sh_g + j);
        float4 y = *reinterpret_cast<const float4*>(sh_h + j);
        float4 ga = *reinterpret_cast<const float4*>(g_i2h + j);
        float4 ba = *reinterpret_cast<const float4*>(be_i2h + j);
        float4 gb = *reinterpret_cast<const float4*>(g_h2h + j);
        float4 bb = *reinterpret_cast<const float4*>(be_h2h + j);
        float4 o;
        o.x = ga.x * ((x.x - m1) * inv1) + ba.x + gb.x * ((y.x - m2) * inv2) + bb.x;
        o.y = ga.y * ((x.y - m1) * inv1) + ba.y + gb.y * ((y.y - m2) * inv2) + bb.y;
        o.z = ga.z * ((x.z - m1) * inv1) + ba.z + gb.z * ((y.z - m2) * inv2) + bb.z;
        o.w = ga.w * ((x.w - m1) * inv1) + ba.w + gb.w * ((y.w - m2) * inv2) + bb.w;
        *reinterpret_cast<float4*>(sh_g + j) = o;
    }
    __syncthreads();

    s = 0.0f; q = 0.0f;
    for (int k = tid * 4; k < HH; k += 1024) {
        float4 ig = *reinterpret_cast<const float4*>(sh_g + k);
        float4 fg = *reinterpret_cast<const float4*>(sh_g + HH + k);
        float4 ug = *reinterpret_cast<const float4*>(sh_g + 2 * HH + k);
        float4 og = *reinterpret_cast<const float4*>(sh_g + 3 * HH + k);
        float4 cv = *reinterpret_cast<const float4*>(c_prev + (size_t)r * HH + k);
        float4 cp;
        cp.x = cv.x * sigm(fg.x + 1.0f) + fast_tanh(ug.x) * sigm(ig.x);
        cp.y = cv.y * sigm(fg.y + 1.0f) + fast_tanh(ug.y) * sigm(ig.y);
        cp.z = cv.z * sigm(fg.z + 1.0f) + fast_tanh(ug.z) * sigm(ig.z);
        cp.w = cv.w * sigm(fg.w + 1.0f) + fast_tanh(ug.w) * sigm(ig.w);
        *reinterpret_cast<float4*>(sh_h + k) = cp;
        *reinterpret_cast<float4*>(sh_h + HH + k) = og;
        s += cp.x + cp.y + cp.z + cp.w;
        q += cp.x * cp.x + cp.y * cp.y + cp.z * cp.z + cp.w * cp.w;
    }
    block_reduce2(s, q);
    const float m3 = s / (float)HH;
    const float v3 = (q - s * s / (float)HH) / (float)(HH - 1);
    const float inv3 = 1.0f / (sqrtf(v3) + EPS);

    float* out_h = out;
    float* out_c = out + (size_t)MB * HH;
    for (int k = tid * 4; k < HH; k += 1024) {
        float4 cp = *reinterpret_cast<const float4*>(sh_h + k);
        float4 og = *reinterpret_cast<const float4*>(sh_h + HH + k);
        float4 gc = *reinterpret_cast<const float4*>(g_c + k);
        float4 bc = *reinterpret_cast<const float4*>(be_c + k);
        float4 c, h;
        c.x = gc.x * ((cp.x - m3) * inv3) + bc.x;
        c.y = gc.y * ((cp.y - m3) * inv3) + bc.y;
        c.z = gc.z * ((cp.z - m3) * inv3) + bc.z;
        c.w = gc.w * ((cp.w - m3) * inv3) + bc.w;
        h.x = sigm(og.x) * fast_tanh(c.x);
        h.y = sigm(og.y) * fast_tanh(c.y);
        h.z = sigm(og.z) * fast_tanh(c.z);
        h.w = sigm(og.w) * fast_tanh(c.w);
        *reinterpret_cast<float4*>(out_h + (size_t)r * HH + k) = h;
        *reinterpret_cast<float4*>(out_c + (size_t)r * HH + k) = c;
    }
}

// ========================= launch =========================
extern "C" void kernel_launch(void* const* d_in, const int* in_sizes, int n_in,
                              void* d_out, int out_size)
{
    const float* input  = (const float*)d_in[0];
    const float* h_prev = (const float*)d_in[1];
    const float* c_prev = (const float*)d_in[2];
    const float* w_i2h  = (const float*)d_in[3];
    const float* b_i2h  = (const float*)d_in[4];
    const float* w_h2h  = (const float*)d_in[5];
    const float* b_h2h  = (const float*)d_in[6];
    const float* g_i2h  = (const float*)d_in[7];
    const float* be_i2h = (const float*)d_in[8];
    const float* g_h2h  = (const float*)d_in[9];
    const float* be_h2h = (const float*)d_in[10];
    const float* g_c    = (const float*)d_in[11];
    const float* be_c   = (const float*)d_in[12];
    float* out = (float*)d_out;

    cudaFuncSetAttribute(gemm_tf32, cudaFuncAttributeMaxDynamicSharedMemorySize, GSMEM_TOTAL);

    // tf32 operand prep in mma fragment-major order
    convert_A<<<(MTOT / 16) * (KK / 8) / 8, 256>>>(input, h_prev);            // 8192 blocks
    convert_B<<<dim3((NN / 8) * (KK / 8) / 8, 1, 2), 256>>>(w_i2h, w_h2h);    // 8192 x 2 blocks

    // fused dual GEMM on tf32 HMMA (single pass, K=1024)
    gemm_tf32<<<dim3(NN / BN, MTOT / BM), GTHREADS, GSMEM_TOTAL>>>();

    lstm_epilogue<<<MB, 256>>>(c_prev, b_i2h, b_h2h, g_i2h, be_i2h,
                               g_h2h, be_h2h, g_c, be_c, out);
}

// round 13
// speedup vs baseline: 1.3643x; 1.0042x over previous
#include <cuda_runtime.h>
#include <math.h>
#include <stdint.h>

// Problem constants (B=4096, I=H=1024, 4H=4096)
#define MB 4096
#define KK 1024
#define NN 4096
#define HH 1024
#define MTOT 8192              // input rows stacked on h_prev rows

// ---------------- scratch (allocation-free: device globals) ----------------
// A' fragment-major: [mb(64)][ks(32)][mt(8)][kc(4)][lane(32)][j(4)] floats = 32 MB
__device__ __align__(1024) float g_Atf[(size_t)MTOT * KK];
// B' fragment-major: [mat][nb(16)][ks(32)][nt(32)][kc(4)][lane(32)][jb(2)] floats = 32 MB
__device__ __align__(1024) float g_Btf[2][(size_t)NN * KK];
__device__ float g_pre_i2h[(size_t)MB * NN];                               // 64 MB
__device__ float g_pre_h2h[(size_t)MB * NN];                               // 64 MB

// ========================= PTX helpers =========================
__device__ __forceinline__ uint32_t smem_u32(const void* p) {
    uint32_t a;
    asm("{ .reg .u64 t; cvta.to.shared.u64 t, %1; cvt.u32.u64 %0, t; }" : "=r"(a) : "l"(p));
    return a;
}
__device__ __forceinline__ void cp_async16(uint32_t saddr, const void* gaddr) {
    asm volatile("cp.async.cg.shared.global [%0], [%1], 16;" :: "r"(saddr), "l"(gaddr));
}
#define CP_COMMIT() asm volatile("cp.async.commit_group;" ::: "memory")
#define CP_WAIT_GROUP(n) asm volatile("cp.async.wait_group %0;" :: "n"(n) : "memory")

__device__ __forceinline__ uint32_t f2tf32(float x) {
    uint32_t r;
    asm("cvt.rna.tf32.f32 %0, %1;" : "=r"(r) : "f"(x));
    return r;
}
__device__ __forceinline__ void mma_tf32(float* d, uint32_t a0, uint32_t a1, uint32_t a2, uint32_t a3,
                                         uint32_t b0, uint32_t b1) {
    asm volatile("mma.sync.aligned.m16n8k8.row.col.f32.tf32.tf32.f32 "
        "{%0,%1,%2,%3}, {%4,%5,%6,%7}, {%8,%9}, {%0,%1,%2,%3};"
        : "+f"(d[0]), "+f"(d[1]), "+f"(d[2]), "+f"(d[3])
        : "r"(a0), "r"(a1), "r"(a2), "r"(a3), "r"(b0), "r"(b1));
}

// ========================= conversion kernels =========================
// A': one thread per (mb,ks,mt,kc,lane); writes its 4 fragment regs as float4.
// a0=A[m][k], a1=A[m+8][k], a2=A[m][k+4], a3=A[m+8][k+4]; m=mb*128+mt*16+(l>>2), k=ks*32+kc*8+(l&3)
__global__ __launch_bounds__(256)
void convert_A(const float* __restrict__ input, const float* __restrict__ h_prev)
{
    const uint32_t t = blockIdx.x * 256 + threadIdx.x;   // 0 .. 2^21-1
    const int l  = t & 31;
    const int kc = (t >> 5) & 3;
    const int mt = (t >> 7) & 7;
    const int ks = (t >> 10) & 31;
    const int mb = t >> 15;
    const int m = mb * 128 + mt * 16 + (l >> 2);
    const int k = ks * 32 + kc * 8 + (l & 3);
    const float* src = (m < MB) ? (input + (size_t)m * KK) : (h_prev + (size_t)(m - MB) * KK);
    const float* src8 = (m + 8 < MB) ? (input + (size_t)(m + 8) * KK) : (h_prev + (size_t)(m + 8 - MB) * KK);
    uint4 o;
    o.x = f2tf32(src[k]);
    o.y = f2tf32(src8[k]);
    o.z = f2tf32(src[k + 4]);
    o.w = f2tf32(src8[k + 4]);
    *reinterpret_cast<uint4*>(g_Atf + (size_t)t * 4) = o;
}

// B': one thread per (nb,ks,nt,kc,lane); writes b0,b1 as float2.
// b0=w[k][n], b1=w[k+4][n]; n=nb*256+nt*8+(l>>2), k=ks*32+kc*8+(l&3)
__global__ __launch_bounds__(256)
void convert_B(const float* __restrict__ w0, const float* __restrict__ w1)
{
    const uint32_t t = blockIdx.x * 256 + threadIdx.x;   // 0 .. 2^21-1
    const int mat = blockIdx.z;
    const float* w = mat ? w1 : w0;
    const int l  = t & 31;
    const int kc = (t >> 5) & 3;
    const int nt = (t >> 7) & 31;
    const int ks = (t >> 12) & 31;
    const int nb = t >> 17;
    const int n = nb * 256 + nt * 8 + (l >> 2);
    const int k = ks * 32 + kc * 8 + (l & 3);
    uint2 o;
    o.x = f2tf32(w[(size_t)k * NN + n]);
    o.y = f2tf32(w[(size_t)(k + 4) * NN + n]);
    *reinterpret_cast<uint2*>(g_Btf[mat] + (size_t)t * 2) = o;
}

// ========================= tf32 mma.sync GEMM =========================
// C[128,256] tiles; operands pre-permuted in fragment-major order.
#define BM 128
#define BN 256
#define BK 32
#define GSTAGES 4
#define NSTEPS (KK / BK)               // 32
#define GTHREADS 256

#define A_STAGE_BYTES (8 * 4 * 32 * 16)    // 16384: [mt][kc][lane][4 floats]
#define B_STAGE_BYTES (32 * 4 * 32 * 8)    // 32768: [nt][kc][lane][2 floats]
#define STAGE_BYTES (A_STAGE_BYTES + B_STAGE_BYTES)   // 49152
#define GSMEM_TOTAL (GSTAGES * STAGE_BYTES)           // 196608

__device__ __forceinline__ void load_stage(uint32_t sbase, int s, int kstage, int tid,
                                           const float* gA, const float* gB)
{
    const uint32_t stage = sbase + s * STAGE_BYTES;
    const float* Asrc = gA + (size_t)kstage * (A_STAGE_BYTES / 4);
    const float* Bsrc = gB + (size_t)kstage * (B_STAGE_BYTES / 4);
    #pragma unroll
    for (int j = 0; j < 12; j++) {
        int idx = tid + j * GTHREADS;   // 0..3071 (16B units)
        if (idx < 1024) {
            cp_async16(stage + idx * 16, Asrc + idx * 4);
        } else {
            int b = idx - 1024;
            cp_async16(stage + A_STAGE_BYTES + b * 16, Bsrc + b * 4);
        }
    }
}

__global__ __launch_bounds__(GTHREADS, 1)
void gemm_tf32()
{
    extern __shared__ char gsm[];
    const uint32_t sbase = smem_u32(gsm);
    const int tid = threadIdx.x;
    const int wid = tid >> 5;
    const int lid = tid & 31;
    const int warp_m = wid >> 2;        // 0..1 -> 64-row slab (4 mtiles)
    const int warp_n = wid & 3;         // 0..3 -> 64-col slab (8 ntiles)

    const int tileN = blockIdx.x;       // 0..15
    const int tileM = blockIdx.y;       // 0..63
    const int mat = (tileM >= 32) ? 1 : 0;
    // A' per (mb): 32 kstages x 16KB; B' per (nb): 32 kstages x 32KB
    const float* gA = g_Atf + (size_t)tileM * 32 * (A_STAGE_BYTES / 4);
    const float* gB = g_Btf[mat] + (size_t)tileN * 32 * (B_STAGE_BYTES / 4);

    float acc[4][8][4];
    #pragma unroll
    for (int mi = 0; mi < 4; mi++)
        #pragma unroll
        for (int ni = 0; ni < 8; ni++)
            #pragma unroll
            for (int r = 0; r < 4; r++)
                acc[mi][ni][r] = 0.0f;

    // prologue: fill first 3 stages (one commit group each)
    load_stage(sbase, 0, 0, tid, gA, gB);
    CP_COMMIT();
    load_stage(sbase, 1, 1, tid, gA, gB);
    CP_COMMIT();
    load_stage(sbase, 2, 2, tid, gA, gB);
    CP_COMMIT();

    // double-buffered kc-slice operand registers
    uint32_t a[2][4][4];
    uint32_t b[2][8][2];

    for (int i = 0; i < NSTEPS; i++) {
        const int s = i & 3;
        // one group committed per iteration (empty in tail) -> <=2 outstanding
        // guarantees stage i's group has landed.
        CP_WAIT_GROUP(2);
        __syncthreads();

        if (i + 3 < NSTEPS)
            load_stage(sbase, (i + 3) & 3, i + 3, tid, gA, gB);
        CP_COMMIT();

        const uint32_t aS = sbase + s * STAGE_BYTES;
        const uint32_t bS = aS + A_STAGE_BYTES;

        // prefetch kc=0 into buffer 0
        #pragma unroll
        for (int mi = 0; mi < 4; mi++) {
            const int mt = warp_m * 4 + mi;
            uint32_t off = aS + (uint32_t)(((mt * 4 + 0) * 32 + lid) * 16);
            asm volatile("ld.shared.v4.b32 {%0,%1,%2,%3}, [%4];"
                : "=r"(a[0][mi][0]), "=r"(a[0][mi][1]), "=r"(a[0][mi][2]), "=r"(a[0][mi][3]) : "r"(off));
        }
        #pragma unroll
        for (int ni = 0; ni < 8; ni++) {
            const int nt = warp_n * 8 + ni;
            uint32_t off = bS + (uint32_t)(((nt * 4 + 0) * 32 + lid) * 8);
            asm volatile("ld.shared.v2.b32 {%0,%1}, [%2];"
                : "=r"(b[0][ni][0]), "=r"(b[0][ni][1]) : "r"(off));
        }

        #pragma unroll
        for (int kc = 0; kc < 4; kc++) {
            const int cur = kc & 1;
            const int nxt = cur ^ 1;
            if (kc < 3) {   // prefetch next kc-slice while current MMAs run
                #pragma unroll
                for (int mi = 0; mi < 4; mi++) {
                    const int mt = warp_m * 4 + mi;
                    uint32_t off = aS + (uint32_t)(((mt * 4 + kc + 1) * 32 + lid) * 16);
                    asm volatile("ld.shared.v4.b32 {%0,%1,%2,%3}, [%4];"
                        : "=r"(a[nxt][mi][0]), "=r"(a[nxt][mi][1]), "=r"(a[nxt][mi][2]), "=r"(a[nxt][mi][3]) : "r"(off));
                }
                #pragma unroll
                for (int ni = 0; ni < 8; ni++) {
                    const int nt = warp_n * 8 + ni;
                    uint32_t off = bS + (uint32_t)(((nt * 4 + kc + 1) * 32 + lid) * 8);
                    asm volatile("ld.shared.v2.b32 {%0,%1}, [%2];"
                        : "=r"(b[nxt][ni][0]), "=r"(b[nxt][ni][1]) : "r"(off));
                }
            }
            #pragma unroll
            for (int mi = 0; mi < 4; mi++)
                #pragma unroll
                for (int ni = 0; ni < 8; ni++)
                    mma_tf32(acc[mi][ni], a[cur][mi][0], a[cur][mi][1], a[cur][mi][2], a[cur][mi][3],
                             b[cur][ni][0], b[cur][ni][1]);
        }
    }

    // store C (D layout: d0,d1 -> row lid>>2, cols (lid&3)*2,+1; d2,d3 -> row+8)
    float* gC = ((tileM < 32) ? (g_pre_i2h + (size_t)tileM * BM * NN)
                              : (g_pre_h2h + (size_t)(tileM - 32) * BM * NN))
                + (size_t)tileN * BN;
    const int mrow = warp_m * 64 + (lid >> 2);
    const int ncol = warp_n * 64 + (lid & 3) * 2;
    #pragma unroll
    for (int mi = 0; mi < 4; mi++) {
        #pragma unroll
        for (int ni = 0; ni < 8; ni++) {
            float* p0 = gC + (size_t)(mrow + mi * 16) * NN + ncol + ni * 8;
            float* p1 = gC + (size_t)(mrow + mi * 16 + 8) * NN + ncol + ni * 8;
            *reinterpret_cast<float2*>(p0) = make_float2(acc[mi][ni][0], acc[mi][ni][1]);
            *reinterpret_cast<float2*>(p1) = make_float2(acc[mi][ni][2], acc[mi][ni][3]);
        }
    }
}

// ========================= LN + gates epilogue =========================
#define EPS 1e-6f

__device__ __forceinline__ float sigm(float x) { return 1.0f / (1.0f + __expf(-x)); }
__device__ __forceinline__ float fast_tanh(float x) {
    float ax = fminf(fabsf(x), 15.0f);
    float t = __expf(2.0f * ax);
    float r = (t - 1.0f) / (t + 1.0f);
    return copysignf(r, x);
}

__device__ void block_reduce2(float& s, float& q)
{
    __shared__ __align__(16) float rs[8], rq[8];
    __shared__ float bs, bq;
    #pragma unroll
    for (int o = 16; o > 0; o >>= 1) {
        s += __shfl_down_sync(0xffffffffu, s, o);
        q += __shfl_down_sync(0xffffffffu, q, o);
    }
    const int w = threadIdx.x >> 5, l = threadIdx.x & 31;
    __syncthreads();
    if (l == 0) { rs[w] = s; rq[w] = q; }
    __syncthreads();
    if (threadIdx.x == 0) {
        float a = 0.0f, b = 0.0f;
        #pragma unroll
        for (int i = 0; i < 8; i++) { a += rs[i]; b += rq[i]; }
        bs = a; bq = b;
    }
    __syncthreads();
    s = bs; q = bq;
}

__global__ __launch_bounds__(256)
void lstm_epilogue(const float* __restrict__ c_prev,
                   const float* __restrict__ b_i2h, const float* __restrict__ b_h2h,
                   const float* __restrict__ g_i2h, const float* __restrict__ be_i2h,
                   const float* __restrict__ g_h2h, const float* __restrict__ be_h2h,
                   const float* __restrict__ g_c,   const float* __restrict__ be_c,
                   float* __restrict__ out)
{
    __shared__ __align__(16) float sh_g[NN];
    __shared__ __align__(16) float sh_h[NN];

    const int r = blockIdx.x;
    const int tid = threadIdx.x;
    const float* hi = g_pre_i2h + (size_t)r * NN;
    const float* hh = g_pre_h2h + (size_t)r * NN;

    float s = 0.0f, q = 0.0f;
    for (int j = tid * 4; j < NN; j += 1024) {
        float4 v = *reinterpret_cast<const float4*>(hi + j);
        float4 b = *reinterpret_cast<const float4*>(b_i2h + j);
        v.x += b.x; v.y += b.y; v.z += b.z; v.w += b.w;
        *reinterpret_cast<float4*>(sh_g + j) = v;
        s += v.x + v.y + v.z + v.w;
        q += v.x * v.x + v.y * v.y + v.z * v.z + v.w * v.w;
    }
    block_reduce2(s, q);
    const float m1 = s / (float)NN;
    const float v1 = (q - s * s / (float)NN) / (float)(NN - 1);
    const float inv1 = 1.0f / (sqrtf(v1) + EPS);

    s = 0.0f; q = 0.0f;
    for (int j = tid * 4; j < NN; j += 1024) {
        float4 v = *reinterpret_cast<const float4*>(hh + j);
        float4 b = *reinterpret_cast<const float4*>(b_h2h + j);
        v.x += b.x; v.y += b.y; v.z += b.z; v.w += b.w;
        *reinterpret_cast<float4*>(sh_h + j) = v;
        s += v.x + v.y + v.z + v.w;
        q += v.x * v.x + v.y * v.y + v.z * v.z + v.w * v.w;
    }
    block_reduce2(s, q);
    const float m2 = s / (float)NN;
    const float v2 = (q - s * s / (float)NN) / (float)(NN - 1);
    const float inv2 = 1.0f / (sqrtf(v2) + EPS);

    for (int j = tid * 4; j < NN; j += 1024) {
        float4 x = *reinterpret_cast<const float4*>(sh_g + j);
        float4 y = *reinterpret_cast<const float4*>(sh_h + j);
        float4 ga = *reinterpret_cast<const float4*>(g_i2h + j);
        float4 ba = *reinterpret_cast<const float4*>(be_i2h + j);
        float4 gb = *reinterpret_cast<const float4*>(g_h2h + j);
        float4 bb = *reinterpret_cast<const float4*>(be_h2h + j);
        float4 o;
        o.x = ga.x * ((x.x - m1) * inv1) + ba.x + gb.x * ((y.x - m2) * inv2) + bb.x;
        o.y = ga.y * ((x.y - m1) * inv1) + ba.y + gb.y * ((y.y - m2) * inv2) + bb.y;
        o.z = ga.z * ((x.z - m1) * inv1) + ba.z + gb.z * ((y.z - m2) * inv2) + bb.z;
        o.w = ga.w * ((x.w - m1) * inv1) + ba.w + gb.w * ((y.w - m2) * inv2) + bb.w;
        *reinterpret_cast<float4*>(sh_g + j) = o;
    }
    __syncthreads();

    s = 0.0f; q = 0.0f;
    for (int k = tid * 4; k < HH; k += 1024) {
        float4 ig = *reinterpret_cast<const float4*>(sh_g + k);
        float4 fg = *reinterpret_cast<const float4*>(sh_g + HH + k);
        float4 ug = *reinterpret_cast<const float4*>(sh_g + 2 * HH + k);
        float4 og = *reinterpret_cast<const float4*>(sh_g + 3 * HH + k);
        float4 cv = *reinterpret_cast<const float4*>(c_prev + (size_t)r * HH + k);
        float4 cp;
        cp.x = cv.x * sigm(fg.x + 1.0f) + fast_tanh(ug.x) * sigm(ig.x);
        cp.y = cv.y * sigm(fg.y + 1.0f) + fast_tanh(ug.y) * sigm(ig.y);
        cp.z = cv.z * sigm(fg.z + 1.0f) + fast_tanh(ug.z) * sigm(ig.z);
        cp.w = cv.w * sigm(fg.w + 1.0f) + fast_tanh(ug.w) * sigm(ig.w);
        *reinterpret_cast<float4*>(sh_h + k) = cp;
        *reinterpret_cast<float4*>(sh_h + HH + k) = og;
        s += cp.x + cp.y + cp.z + cp.w;
        q += cp.x * cp.x + cp.y * cp.y + cp.z * cp.z + cp.w * cp.w;
    }
    block_reduce2(s, q);
    const float m3 = s / (float)HH;
    const float v3 = (q - s * s / (float)HH) / (float)(HH - 1);
    const float inv3 = 1.0f / (sqrtf(v3) + EPS);

    float* out_h = out;
    float* out_c = out + (size_t)MB * HH;
    for (int k = tid * 4; k < HH; k += 1024) {
        float4 cp = *reinterpret_cast<const float4*>(sh_h + k);
        float4 og = *reinterpret_cast<const float4*>(sh_h + HH + k);
        float4 gc = *reinterpret_cast<const float4*>(g_c + k);
        float4 bc = *reinterpret_cast<const float4*>(be_c + k);
        float4 c, h;
        c.x = gc.x * ((cp.x - m3) * inv3) + bc.x;
        c.y = gc.y * ((cp.y - m3) * inv3) + bc.y;
        c.z = gc.z * ((cp.z - m3) * inv3) + bc.z;
        c.w = gc.w * ((cp.w - m3) * inv3) + bc.w;
        h.x = sigm(og.x) * fast_tanh(c.x);
        h.y = sigm(og.y) * fast_tanh(c.y);
        h.z = sigm(og.z) * fast_tanh(c.z);
        h.w = sigm(og.w) * fast_tanh(c.w);
        *reinterpret_cast<float4*>(out_h + (size_t)r * HH + k) = h;
        *reinterpret_cast<float4*>(out_c + (size_t)r * HH + k) = c;
    }
}

// ========================= launch =========================
extern "C" void kernel_launch(void* const* d_in, const int* in_sizes, int n_in,
                              void* d_out, int out_size)
{
    const float* input  = (const float*)d_in[0];
    const float* h_prev = (const float*)d_in[1];
    const float* c_prev = (const float*)d_in[2];
    const float* w_i2h  = (const float*)d_in[3];
    const float* b_i2h  = (const float*)d_in[4];
    const float* w_h2h  = (const float*)d_in[5];
    const float* b_h2h  = (const float*)d_in[6];
    const float* g_i2h  = (const float*)d_in[7];
    const float* be_i2h = (const float*)d_in[8];
    const float* g_h2h  = (const float*)d_in[9];
    const float* be_h2h = (const float*)d_in[10];
    const float* g_c    = (const float*)d_in[11];
    const float* be_c   = (const float*)d_in[12];
    float* out = (float*)d_out;

    cudaFuncSetAttribute(gemm_tf32, cudaFuncAttributeMaxDynamicSharedMemorySize, GSMEM_TOTAL);

    // tf32 operand prep in mma fragment-major order
    convert_A<<<(MTOT / 16) * (KK / 8) / 8, 256>>>(input, h_prev);            // 8192 blocks
    convert_B<<<dim3((NN / 8) * (KK / 8) / 8, 1, 2), 256>>>(w_i2h, w_h2h);    // 8192 x 2 blocks

    // fused dual GEMM on tf32 HMMA (single pass, K=1024)
    gemm_tf32<<<dim3(NN / BN, MTOT / BM), GTHREADS, GSMEM_TOTAL>>>();

    lstm_epilogue<<<MB, 256>>>(c_prev, b_i2h, b_h2h, g_i2h, be_i2h,
                               g_h2h, be_h2h, g_c, be_c, out);
}